// round 4
// baseline (speedup 1.0000x reference)
#include <cuda_runtime.h>
#include <cstdint>

// ---------------------------------------------------------------------------
// LightGCN on B200 (sm_100a)
//   N_NODES = 256000, EMBED_DIM = 64, N_EDGES = 4,000,000, 3 layers
//   out = (x0 + x1 + x2 + x3) / 4, x_{l+1}[r] = sum_e norm[e] * x_l[col[e]]
//   norm[e] = deg(row[e])^-1/2 * deg(col[e])^-1/2, deg from row only.
//
// NOTE: reference uses jnp.int64 for edge_index but JAX defaults to x64
// disabled -> actual dtype is very likely int32. We detect on-device.
// ---------------------------------------------------------------------------

#define NUM_USERS   100000
#define NUM_ST      150000
#define NUM_INTENTS 6000
#define N_NODES     (NUM_USERS + NUM_ST + NUM_INTENTS)   // 256000
#define EMBED_DIM   64
#define N_EDGES     4000000
#define NUM_LAYERS  3

#define NFLOATS     (N_NODES * EMBED_DIM)        // 16,384,000
#define NF4         (NFLOATS / 4)                // 4,096,000
#define DETECT_N    4096

// Scratch (device globals: allocation-guard safe)
__device__ __align__(16) float g_bufA[NFLOATS];
__device__ __align__(16) float g_bufB[NFLOATS];
__device__ float g_dis[N_NODES];
__device__ int   g_deg[N_NODES];
__device__ float g_norm[N_EDGES];
__device__ int   g_row[N_EDGES];
__device__ int   g_col[N_EDGES];
__device__ int   g_not64;   // 1 => data is NOT valid int64 => treat as int32

// ---------------------------------------------------------------------------

__global__ void k_zero_deg() {
    int i = blockIdx.x * blockDim.x + threadIdx.x;
    if (i < N_NODES) g_deg[i] = 0;
    if (i == 0) g_not64 = 0;
}

// Dtype detection: interpret the first DETECT_N words as int64. Genuine
// int64 indices all lie in [0, N_NODES); int32 data read as int64 fuses
// two indices -> value >= 2^32 almost surely.
__global__ void k_detect(const long long* __restrict__ ei) {
    int e = blockIdx.x * blockDim.x + threadIdx.x;
    if (e >= DETECT_N) return;
    long long v = ei[e];
    if (v < 0 || v >= N_NODES) atomicOr(&g_not64, 1);
}

// Count degrees from row; pack indices -> int32 (dtype chosen by g_not64).
// Bounds-guard: bad index -> sentinel -1 (skipped downstream).
__global__ void k_deg_and_pack(const void* __restrict__ eiv) {
    int e = blockIdx.x * blockDim.x + threadIdx.x;
    if (e >= N_EDGES) return;
    long long r64, c64;
    if (g_not64) {
        const int* ei32 = (const int*)eiv;
        r64 = ei32[e];
        c64 = ei32[N_EDGES + e];
    } else {
        const long long* ei64 = (const long long*)eiv;
        r64 = ei64[e];
        c64 = ei64[(long long)N_EDGES + e];
    }
    int r = (r64 >= 0 && r64 < N_NODES) ? (int)r64 : -1;
    int c = (c64 >= 0 && c64 < N_NODES) ? (int)c64 : -1;
    g_row[e] = r;
    g_col[e] = c;
    if (r >= 0) atomicAdd(&g_deg[r], 1);
}

__global__ void k_dis() {
    int i = blockIdx.x * blockDim.x + threadIdx.x;
    if (i >= N_NODES) return;
    int d = g_deg[i];
    g_dis[i] = (d > 0) ? rsqrtf((float)d) : 0.0f;
}

__global__ void k_norm() {
    int e = blockIdx.x * blockDim.x + threadIdx.x;
    if (e >= N_EDGES) return;
    int r = g_row[e], c = g_col[e];
    g_norm[e] = (r >= 0 && c >= 0) ? g_dis[r] * g_dis[c] : 0.0f;
}

// out = emb (accumulator init), x = emb (layer-0 state), xn = 0
__global__ void k_init(const float4* __restrict__ emb,
                       float4* __restrict__ out,
                       float4* __restrict__ x,
                       float4* __restrict__ xn) {
    int i = blockIdx.x * blockDim.x + threadIdx.x;
    if (i >= NF4) return;
    float4 v = emb[i];
    out[i] = v;
    x[i]   = v;
    xn[i]  = make_float4(0.f, 0.f, 0.f, 0.f);
}

// Scatter SpMM: 16 threads per edge, one float4 chunk each.
// red.global.add.v4.f32 -> 1 vector atomic per 16 B (sm_90+).
__global__ void k_scatter(const float4* __restrict__ x,
                          float* __restrict__ xn) {
    int t = blockIdx.x * blockDim.x + threadIdx.x;      // < 64M
    int e = t >> 4;
    int c = t & 15;
    if (e >= N_EDGES) return;
    int   row = __ldg(&g_row[e]);
    int   col = __ldg(&g_col[e]);
    if ((row | col) < 0) return;
    float w = __ldg(&g_norm[e]);
    float4 v = __ldg(&x[(long long)col * 16 + c]);
    float4 r;
    r.x = w * v.x; r.y = w * v.y; r.z = w * v.z; r.w = w * v.w;
    float* dst = xn + (long long)row * EMBED_DIM + c * 4;
    asm volatile("red.global.add.v4.f32 [%0], {%1, %2, %3, %4};"
                 :: "l"(dst), "f"(r.x), "f"(r.y), "f"(r.z), "f"(r.w)
                 : "memory");
}

// out += xn; zero the *other* buffer (which becomes next layer's target)
__global__ void k_accum_zero(float4* __restrict__ out,
                             const float4* __restrict__ xn,
                             float4* __restrict__ zbuf) {
    int i = blockIdx.x * blockDim.x + threadIdx.x;
    if (i >= NF4) return;
    float4 a = out[i];
    float4 b = xn[i];
    a.x += b.x; a.y += b.y; a.z += b.z; a.w += b.w;
    out[i] = a;
    zbuf[i] = make_float4(0.f, 0.f, 0.f, 0.f);
}

// out *= 1/(NUM_LAYERS+1)
__global__ void k_scale(float4* __restrict__ out) {
    int i = blockIdx.x * blockDim.x + threadIdx.x;
    if (i >= NF4) return;
    const float s = 1.0f / (float)(NUM_LAYERS + 1);
    float4 a = out[i];
    a.x *= s; a.y *= s; a.z *= s; a.w *= s;
    out[i] = a;
}

// ---------------------------------------------------------------------------

extern "C" void kernel_launch(void* const* d_in, const int* in_sizes, int n_in,
                              void* d_out, int out_size) {
    // Input-order detection by element count: embedding = 16,384,000,
    // edge_index = 8,000,000 (count is dtype-independent).
    int ei_idx = 1, emb_idx = 0;
    if (n_in >= 2 && in_sizes[0] == 2 * N_EDGES) { ei_idx = 0; emb_idx = 1; }

    const float* emb = (const float*)d_in[emb_idx];
    const void*  ei  = d_in[ei_idx];
    float*       out = (float*)d_out;

    const int TB = 256;
    const int node_blocks = (N_NODES + TB - 1) / TB;
    const int edge_blocks = (N_EDGES + TB - 1) / TB;
    const int f4_blocks   = (NF4 + TB - 1) / TB;
    const int scat_blocks = (N_EDGES * 16 + TB - 1) / TB;   // 64M threads

    float* bufA;  cudaGetSymbolAddress((void**)&bufA, g_bufA);
    float* bufB;  cudaGetSymbolAddress((void**)&bufB, g_bufB);

    // Preprocess
    k_zero_deg<<<node_blocks, TB>>>();
    k_detect<<<(DETECT_N + TB - 1) / TB, TB>>>((const long long*)ei);
    k_deg_and_pack<<<edge_blocks, TB>>>(ei);
    k_dis<<<node_blocks, TB>>>();
    k_norm<<<edge_blocks, TB>>>();

    // out = x = emb, xn = 0
    k_init<<<f4_blocks, TB>>>((const float4*)emb, (float4*)out,
                              (float4*)bufA, (float4*)bufB);

    // 3 propagation layers with ping-pong scratch
    float* x  = bufA;
    float* xn = bufB;
    for (int l = 0; l < NUM_LAYERS; ++l) {
        k_scatter<<<scat_blocks, TB>>>((const float4*)x, xn);
        // out += xn; zero x (old state buffer becomes next layer's target)
        k_accum_zero<<<f4_blocks, TB>>>((float4*)out, (const float4*)xn,
                                        (float4*)x);
        float* tmp = x; x = xn; xn = tmp;
    }

    k_scale<<<f4_blocks, TB>>>((float4*)out);
}

// round 5
// speedup vs baseline: 2.0436x; 2.0436x over previous
#include <cuda_runtime.h>
#include <cstdint>

// ---------------------------------------------------------------------------
// LightGCN on B200 (sm_100a) — CSR-gather formulation (no atomics in layers)
//   N_NODES = 256000, EMBED_DIM = 64, N_EDGES = 4,000,000, 3 layers
//   out = (x0 + x1 + x2 + x3) / 4, x_{l+1}[r] = sum_e norm[e] * x_l[col[e]]
//   norm[e] = deg(row[e])^-1/2 * deg(col[e])^-1/2, deg from row only.
// edge_index dtype detected on device (JAX x64-off => int32 in practice).
// ---------------------------------------------------------------------------

#define NUM_USERS   100000
#define NUM_ST      150000
#define NUM_INTENTS 6000
#define N_NODES     (NUM_USERS + NUM_ST + NUM_INTENTS)   // 256000
#define EMBED_DIM   64
#define N_EDGES     4000000
#define NUM_LAYERS  3

#define NFLOATS     (N_NODES * EMBED_DIM)        // 16,384,000
#define NF4         (NFLOATS / 4)                // 4,096,000
#define DETECT_N    4096

#define SCAN_BLOCK  1024
#define NBLK        (N_NODES / SCAN_BLOCK)       // 250 (exact)

// Scratch (device globals: allocation-guard safe)
__device__ __align__(16) float g_bufA[NFLOATS];
__device__ __align__(16) float g_bufB[NFLOATS];
__device__ float g_dis[N_NODES];
__device__ int   g_deg[N_NODES];
__device__ int   g_start[N_NODES];     // CSR row start (exclusive scan)
__device__ int   g_cursor[N_NODES];    // fill cursor; after fill = row end
__device__ int   g_bsum[NBLK];
__device__ int   g_bsumx[NBLK];
__device__ int   g_row[N_EDGES];
__device__ int   g_col[N_EDGES];
__device__ __align__(16) int2 g_csr[N_EDGES];   // (col, bitcast norm)
__device__ int   g_not64;   // 1 => edge data is int32

// ---------------------------------------------------------------------------

__global__ void k_zero_deg() {
    int i = blockIdx.x * blockDim.x + threadIdx.x;
    if (i < N_NODES) g_deg[i] = 0;
    if (i == 0) g_not64 = 0;
}

// Dtype detection: genuine int64 indices all lie in [0, N_NODES); int32 data
// read as int64 fuses two indices -> value >= 2^32 almost surely.
__global__ void k_detect(const long long* __restrict__ ei) {
    int e = blockIdx.x * blockDim.x + threadIdx.x;
    if (e >= DETECT_N) return;
    long long v = ei[e];
    if (v < 0 || v >= N_NODES) atomicOr(&g_not64, 1);
}

// Degrees from row; pack indices -> int32. Bad index -> sentinel -1.
__global__ void k_deg_and_pack(const void* __restrict__ eiv) {
    int e = blockIdx.x * blockDim.x + threadIdx.x;
    if (e >= N_EDGES) return;
    long long r64, c64;
    if (g_not64) {
        const int* ei32 = (const int*)eiv;
        r64 = ei32[e];
        c64 = ei32[N_EDGES + e];
    } else {
        const long long* ei64 = (const long long*)eiv;
        r64 = ei64[e];
        c64 = ei64[(long long)N_EDGES + e];
    }
    int r = (r64 >= 0 && r64 < N_NODES) ? (int)r64 : -1;
    int c = (c64 >= 0 && c64 < N_NODES) ? (int)c64 : -1;
    g_row[e] = r;
    g_col[e] = c;
    if (r >= 0) atomicAdd(&g_deg[r], 1);
}

__global__ void k_dis() {
    int i = blockIdx.x * blockDim.x + threadIdx.x;
    if (i >= N_NODES) return;
    int d = g_deg[i];
    g_dis[i] = (d > 0) ? rsqrtf((float)d) : 0.0f;
}

// ---- exclusive prefix sum over g_deg (3 kernels) ----

__global__ void k_scan1() {
    __shared__ int sh[SCAN_BLOCK];
    int i = blockIdx.x * SCAN_BLOCK + threadIdx.x;
    int v = g_deg[i];
    sh[threadIdx.x] = v;
    __syncthreads();
    for (int off = 1; off < SCAN_BLOCK; off <<= 1) {
        int t = (threadIdx.x >= off) ? sh[threadIdx.x - off] : 0;
        __syncthreads();
        sh[threadIdx.x] += t;
        __syncthreads();
    }
    g_start[i] = sh[threadIdx.x];   // inclusive-within-block (temp)
    if (threadIdx.x == SCAN_BLOCK - 1) g_bsum[blockIdx.x] = sh[threadIdx.x];
}

__global__ void k_scan2() {   // single block of 256 threads, NBLK=250
    __shared__ int sh[256];
    int v = (threadIdx.x < NBLK) ? g_bsum[threadIdx.x] : 0;
    sh[threadIdx.x] = v;
    __syncthreads();
    for (int off = 1; off < 256; off <<= 1) {
        int t = (threadIdx.x >= off) ? sh[threadIdx.x - off] : 0;
        __syncthreads();
        sh[threadIdx.x] += t;
        __syncthreads();
    }
    if (threadIdx.x < NBLK) g_bsumx[threadIdx.x] = sh[threadIdx.x] - v; // exclusive
}

__global__ void k_scan3() {
    int i = blockIdx.x * blockDim.x + threadIdx.x;
    if (i >= N_NODES) return;
    int excl = g_start[i] - g_deg[i] + g_bsumx[i / SCAN_BLOCK];
    g_start[i]  = excl;
    g_cursor[i] = excl;
}

// Fill CSR pairs (col, norm). Order within a row is irrelevant (sum).
__global__ void k_fill() {
    int e = blockIdx.x * blockDim.x + threadIdx.x;
    if (e >= N_EDGES) return;
    int r = g_row[e], c = g_col[e];
    if ((r | c) < 0) return;
    float w = g_dis[r] * g_dis[c];
    int p = atomicAdd(&g_cursor[r], 1);
    g_csr[p] = make_int2(c, __float_as_int(w));
}

// out = 0.25*emb (accumulator), x = emb (layer-0 state)
__global__ void k_init(const float4* __restrict__ emb,
                       float4* __restrict__ out,
                       float4* __restrict__ x) {
    int i = blockIdx.x * blockDim.x + threadIdx.x;
    if (i >= NF4) return;
    float4 v = emb[i];
    x[i] = v;
    float4 o;
    o.x = 0.25f * v.x; o.y = 0.25f * v.y; o.z = 0.25f * v.z; o.w = 0.25f * v.w;
    out[i] = o;
}

// Gather SpMM: 16 threads per row, one float4 lane each.
// acc = sum_{e in row} norm[e] * x[col[e]]; xn[row] = acc (if !last);
// out[row] += 0.25*acc. No atomics.
__global__ void k_gather(const float4* __restrict__ x,
                         float4* __restrict__ xn,
                         float4* __restrict__ out,
                         int last) {
    int t = blockIdx.x * blockDim.x + threadIdx.x;   // 4,096,000 threads exact
    int r = t >> 4;
    int c = t & 15;
    if (r >= N_NODES) return;
    int start = g_start[r];
    int end   = g_cursor[r];          // after fill: start + n_valid_edges
    // Half-warp shuffle mask: lanes 0-15 or 16-31 (each group = one row).
    unsigned gmask = 0xFFFFu << (threadIdx.x & 16);

    float4 acc = make_float4(0.f, 0.f, 0.f, 0.f);
    for (int base = start; base < end; base += 16) {
        int n = min(16, end - base);
        int2 pr = make_int2(0, 0);
        if (c < n) pr = __ldg(&g_csr[base + c]);
        #pragma unroll 4
        for (int j = 0; j < n; ++j) {
            int   col = __shfl_sync(gmask, pr.x, j, 16);
            float w   = __int_as_float(__shfl_sync(gmask, pr.y, j, 16));
            float4 v  = __ldg(&x[col * 16 + c]);
            acc.x += w * v.x; acc.y += w * v.y;
            acc.z += w * v.z; acc.w += w * v.w;
        }
    }
    int idx = r * 16 + c;
    if (!last) xn[idx] = acc;
    float4 o = out[idx];
    o.x += 0.25f * acc.x; o.y += 0.25f * acc.y;
    o.z += 0.25f * acc.z; o.w += 0.25f * acc.w;
    out[idx] = o;
}

// ---------------------------------------------------------------------------

extern "C" void kernel_launch(void* const* d_in, const int* in_sizes, int n_in,
                              void* d_out, int out_size) {
    // Input-order detection by element count (dtype-independent):
    // embedding = 16,384,000 elements, edge_index = 8,000,000.
    int ei_idx = 1, emb_idx = 0;
    if (n_in >= 2 && in_sizes[0] == 2 * N_EDGES) { ei_idx = 0; emb_idx = 1; }

    const float* emb = (const float*)d_in[emb_idx];
    const void*  ei  = d_in[ei_idx];
    float*       out = (float*)d_out;

    const int TB = 256;
    const int node_blocks = (N_NODES + TB - 1) / TB;
    const int edge_blocks = (N_EDGES + TB - 1) / TB;
    const int f4_blocks   = (NF4 + TB - 1) / TB;
    const int gat_blocks  = (N_NODES * 16 + TB - 1) / TB;   // 4M threads

    float* bufA;  cudaGetSymbolAddress((void**)&bufA, g_bufA);
    float* bufB;  cudaGetSymbolAddress((void**)&bufB, g_bufB);

    // ---- preprocess: degrees, dis, CSR ----
    k_zero_deg<<<node_blocks, TB>>>();
    k_detect<<<(DETECT_N + TB - 1) / TB, TB>>>((const long long*)ei);
    k_deg_and_pack<<<edge_blocks, TB>>>(ei);
    k_dis<<<node_blocks, TB>>>();
    k_scan1<<<NBLK, SCAN_BLOCK>>>();
    k_scan2<<<1, 256>>>();
    k_scan3<<<node_blocks, TB>>>();
    k_fill<<<edge_blocks, TB>>>();

    // ---- out = emb/4, x = emb ----
    k_init<<<f4_blocks, TB>>>((const float4*)emb, (float4*)out, (float4*)bufA);

    // ---- 3 gather layers (ping-pong), epilogue fused ----
    float* x  = bufA;
    float* xn = bufB;
    for (int l = 0; l < NUM_LAYERS; ++l) {
        int last = (l == NUM_LAYERS - 1);
        k_gather<<<gat_blocks, TB>>>((const float4*)x, (float4*)xn,
                                     (float4*)out, last);
        float* tmp = x; x = xn; xn = tmp;
    }
}

// round 6
// speedup vs baseline: 2.5606x; 1.2530x over previous
#include <cuda_runtime.h>
#include <cstdint>

// ---------------------------------------------------------------------------
// LightGCN on B200 (sm_100a) — CSR-gather, fused epilogue, minimal traffic
//   N_NODES = 256000, EMBED_DIM = 64, N_EDGES = 4,000,000, 3 layers
//   out = (x0 + x1 + x2 + x3) / 4, x_{l+1}[r] = sum_e norm[e] * x_l[col[e]]
//   norm[e] = deg(row[e])^-1/2 * deg(col[e])^-1/2, deg from row only.
// edge_index dtype detected on device (JAX x64-off => int32 in practice).
// ---------------------------------------------------------------------------

#define NUM_USERS   100000
#define NUM_ST      150000
#define NUM_INTENTS 6000
#define N_NODES     (NUM_USERS + NUM_ST + NUM_INTENTS)   // 256000
#define EMBED_DIM   64
#define N_EDGES     4000000
#define NUM_LAYERS  3

#define NFLOATS     (N_NODES * EMBED_DIM)        // 16,384,000
#define NF4         (NFLOATS / 4)                // 4,096,000
#define DETECT_N    4096

#define SCAN_BLOCK  1024
#define NBLK        (N_NODES / SCAN_BLOCK)       // 250 (exact)

// Scratch (device globals: allocation-guard safe)
__device__ __align__(16) float g_bufA[NFLOATS];   // x1
__device__ __align__(16) float g_bufB[NFLOATS];   // x2
__device__ float g_dis[N_NODES];
__device__ int   g_deg[N_NODES];
__device__ int   g_start[N_NODES];     // CSR row start (exclusive scan)
__device__ int   g_cursor[N_NODES];    // fill cursor; after fill = row end
__device__ int   g_bsum[NBLK];
__device__ int   g_bsumx[NBLK];
__device__ __align__(16) int2 g_csr[N_EDGES];   // (col, bitcast norm)
__device__ int   g_not64;   // 1 => edge data is int32

// ---------------------------------------------------------------------------

// Zero degrees + dtype detection in one launch.
// Genuine int64 indices all lie in [0, N_NODES); int32 data read as int64
// fuses two indices -> value >= 2^32 almost surely.
__global__ void k_zero_detect(const long long* __restrict__ ei) {
    int i = blockIdx.x * blockDim.x + threadIdx.x;
    if (i < N_NODES) g_deg[i] = 0;
    if (i == 0) g_not64 = 0;
    __threadfence();
    if (i < DETECT_N) {
        long long v = ei[i];
        if (v < 0 || v >= N_NODES) atomicOr(&g_not64, 1);
    }
}

// Degree histogram straight from edge_index (row half only).
__global__ void k_deg(const void* __restrict__ eiv) {
    int e = blockIdx.x * blockDim.x + threadIdx.x;
    if (e >= N_EDGES) return;
    long long r64;
    if (g_not64) r64 = ((const int*)eiv)[e];
    else         r64 = ((const long long*)eiv)[e];
    if (r64 >= 0 && r64 < N_NODES) atomicAdd(&g_deg[(int)r64], 1);
}

__global__ void k_dis() {
    int i = blockIdx.x * blockDim.x + threadIdx.x;
    if (i >= N_NODES) return;
    int d = g_deg[i];
    g_dis[i] = (d > 0) ? rsqrtf((float)d) : 0.0f;
}

// ---- exclusive prefix sum over g_deg (3 kernels) ----

__global__ void k_scan1() {
    __shared__ int sh[SCAN_BLOCK];
    int i = blockIdx.x * SCAN_BLOCK + threadIdx.x;
    int v = g_deg[i];
    sh[threadIdx.x] = v;
    __syncthreads();
    for (int off = 1; off < SCAN_BLOCK; off <<= 1) {
        int t = (threadIdx.x >= off) ? sh[threadIdx.x - off] : 0;
        __syncthreads();
        sh[threadIdx.x] += t;
        __syncthreads();
    }
    g_start[i] = sh[threadIdx.x];   // inclusive-within-block (temp)
    if (threadIdx.x == SCAN_BLOCK - 1) g_bsum[blockIdx.x] = sh[threadIdx.x];
}

__global__ void k_scan2() {   // single block of 256 threads, NBLK=250
    __shared__ int sh[256];
    int v = (threadIdx.x < NBLK) ? g_bsum[threadIdx.x] : 0;
    sh[threadIdx.x] = v;
    __syncthreads();
    for (int off = 1; off < 256; off <<= 1) {
        int t = (threadIdx.x >= off) ? sh[threadIdx.x - off] : 0;
        __syncthreads();
        sh[threadIdx.x] += t;
        __syncthreads();
    }
    if (threadIdx.x < NBLK) g_bsumx[threadIdx.x] = sh[threadIdx.x] - v; // exclusive
}

__global__ void k_scan3() {
    int i = blockIdx.x * blockDim.x + threadIdx.x;
    if (i >= N_NODES) return;
    int excl = g_start[i] - g_deg[i] + g_bsumx[i / SCAN_BLOCK];
    g_start[i]  = excl;
    g_cursor[i] = excl;
}

// Fill CSR pairs (col, norm) straight from edge_index. Row order irrelevant.
__global__ void k_fill(const void* __restrict__ eiv) {
    int e = blockIdx.x * blockDim.x + threadIdx.x;
    if (e >= N_EDGES) return;
    long long r64, c64;
    if (g_not64) {
        const int* ei32 = (const int*)eiv;
        r64 = ei32[e];
        c64 = ei32[N_EDGES + e];
    } else {
        const long long* ei64 = (const long long*)eiv;
        r64 = ei64[e];
        c64 = ei64[(long long)N_EDGES + e];
    }
    if (r64 < 0 || r64 >= N_NODES || c64 < 0 || c64 >= N_NODES) return;
    int r = (int)r64, c = (int)c64;
    float w = g_dis[r] * g_dis[c];
    int p = atomicAdd(&g_cursor[r], 1);
    g_csr[p] = make_int2(c, __float_as_int(w));
}

// ---------------------------------------------------------------------------
// Gather SpMM: 16 threads per row, one float4 lane each.
// acc = sum_{e in row} norm[e] * x[col[e]]
// ---------------------------------------------------------------------------

__device__ __forceinline__ float4 row_gather(const float4* __restrict__ x,
                                             int r, int c, unsigned gmask) {
    int start = g_start[r];
    int end   = g_cursor[r];          // start + n_valid_edges
    float4 acc = make_float4(0.f, 0.f, 0.f, 0.f);
    for (int base = start; base < end; base += 16) {
        int n = min(16, end - base);
        int2 pr = make_int2(0, 0);
        if (c < n) pr = __ldcs(&g_csr[base + c]);   // read-once stream
        #pragma unroll 4
        for (int j = 0; j < n; ++j) {
            int   col = __shfl_sync(gmask, pr.x, j, 16);
            float w   = __int_as_float(__shfl_sync(gmask, pr.y, j, 16));
            float4 v  = __ldg(&x[col * 16 + c]);
            acc.x += w * v.x; acc.y += w * v.y;
            acc.z += w * v.z; acc.w += w * v.w;
        }
    }
    return acc;
}

// Layers 1..2: xn[row] = acc  (streaming store)
__global__ void k_gather(const float4* __restrict__ x,
                         float4* __restrict__ xn) {
    int t = blockIdx.x * blockDim.x + threadIdx.x;   // 4,096,000 threads exact
    int r = t >> 4;
    int c = t & 15;
    if (r >= N_NODES) return;
    unsigned gmask = 0xFFFFu << (threadIdx.x & 16);
    float4 acc = row_gather(x, r, c, gmask);
    __stcs(&xn[r * 16 + c], acc);
}

// Layer 3 + fused epilogue: out = 0.25*(emb + x1 + x2 + acc)
__global__ void k_gather_final(const float4* __restrict__ x2,
                               const float4* __restrict__ emb,
                               const float4* __restrict__ x1,
                               float4* __restrict__ out) {
    int t = blockIdx.x * blockDim.x + threadIdx.x;
    int r = t >> 4;
    int c = t & 15;
    if (r >= N_NODES) return;
    unsigned gmask = 0xFFFFu << (threadIdx.x & 16);
    float4 acc = row_gather(x2, r, c, gmask);
    int idx = r * 16 + c;
    float4 e0 = __ldcs(&emb[idx]);
    float4 a1 = __ldcs(&x1[idx]);
    float4 a2 = __ldcs(&x2[idx]);
    float4 o;
    o.x = 0.25f * (e0.x + a1.x + a2.x + acc.x);
    o.y = 0.25f * (e0.y + a1.y + a2.y + acc.y);
    o.z = 0.25f * (e0.z + a1.z + a2.z + acc.z);
    o.w = 0.25f * (e0.w + a1.w + a2.w + acc.w);
    __stcs(&out[idx], o);
}

// ---------------------------------------------------------------------------

extern "C" void kernel_launch(void* const* d_in, const int* in_sizes, int n_in,
                              void* d_out, int out_size) {
    // Input-order detection by element count (dtype-independent):
    // embedding = 16,384,000 elements, edge_index = 8,000,000.
    int ei_idx = 1, emb_idx = 0;
    if (n_in >= 2 && in_sizes[0] == 2 * N_EDGES) { ei_idx = 0; emb_idx = 1; }

    const float* emb = (const float*)d_in[emb_idx];
    const void*  ei  = d_in[ei_idx];
    float*       out = (float*)d_out;

    const int TB = 256;
    const int node_blocks = (N_NODES + TB - 1) / TB;
    const int edge_blocks = (N_EDGES + TB - 1) / TB;
    const int gat_blocks  = (N_NODES * 16 + TB - 1) / TB;   // 4M threads

    float* bufA;  cudaGetSymbolAddress((void**)&bufA, g_bufA);
    float* bufB;  cudaGetSymbolAddress((void**)&bufB, g_bufB);

    // ---- preprocess: degrees, dis, CSR ----
    k_zero_detect<<<node_blocks, TB>>>((const long long*)ei);
    k_deg<<<edge_blocks, TB>>>(ei);
    k_dis<<<node_blocks, TB>>>();
    k_scan1<<<NBLK, SCAN_BLOCK>>>();
    k_scan2<<<1, 256>>>();
    k_scan3<<<node_blocks, TB>>>();
    k_fill<<<edge_blocks, TB>>>(ei);

    // ---- 3 gather layers; epilogue fused into the last ----
    k_gather<<<gat_blocks, TB>>>((const float4*)emb, (float4*)bufA);   // x1
    k_gather<<<gat_blocks, TB>>>((const float4*)bufA, (float4*)bufB);  // x2
    k_gather_final<<<gat_blocks, TB>>>((const float4*)bufB,
                                       (const float4*)emb,
                                       (const float4*)bufA,
                                       (float4*)out);
}

// round 8
// speedup vs baseline: 3.1649x; 1.2360x over previous
#include <cuda_runtime.h>
#include <cuda_fp16.h>
#include <cstdint>

// ---------------------------------------------------------------------------
// LightGCN on B200 (sm_100a) — CSR-gather, fp16 intermediate states
//   N_NODES = 256000, EMBED_DIM = 64, N_EDGES = 4,000,000, 3 layers
//   out = (x0 + x1 + x2 + x3) / 4, x_{l+1}[r] = dis[r] * sum_e dis[col]*x_l[col]
//   dis = deg^-1/2 (deg from row). Math fp32; x1/x2 stored fp16 (halves the
//   dominant random-gather traffic). edge_index dtype detected on device.
// ---------------------------------------------------------------------------

#define NUM_USERS   100000
#define NUM_ST      150000
#define NUM_INTENTS 6000
#define N_NODES     (NUM_USERS + NUM_ST + NUM_INTENTS)   // 256000
#define EMBED_DIM   64
#define N_EDGES     4000000

#define NFLOATS     (N_NODES * EMBED_DIM)        // 16,384,000
#define DETECT_N    4096

#define SCAN_BLOCK  1024
#define NBLK        (N_NODES / SCAN_BLOCK)       // 250 (exact)

// half2 <-> u32 reinterpret helpers (no named intrinsics exist for this)
__device__ __forceinline__ unsigned h2u(__half2 h) {
    return *reinterpret_cast<unsigned*>(&h);
}
__device__ __forceinline__ __half2 u2h(unsigned u) {
    return *reinterpret_cast<__half2*>(&u);
}

// Scratch (device globals: allocation-guard safe)
__device__ __align__(16) __half g_h1[NFLOATS];   // x1 (fp16)
__device__ __align__(16) __half g_h2[NFLOATS];   // x2 (fp16)
__device__ float g_dis[N_NODES];
__device__ int   g_deg[N_NODES];
__device__ int   g_start[N_NODES];     // CSR row start (exclusive scan)
__device__ int   g_cursor[N_NODES];    // fill cursor; after fill = row end
__device__ int   g_bsum[NBLK];
__device__ int   g_bsumx[NBLK];
__device__ __align__(16) int2 g_csr[N_EDGES];   // (col, bitcast dis[col])
__device__ int   g_not64;   // 1 => edge data is int32

// ---------------------------------------------------------------------------

// Zero degrees + dtype detection in one launch.
// Genuine int64 indices all lie in [0, N_NODES); int32 data read as int64
// fuses two indices -> value >= 2^32 almost surely.
__global__ void k_zero_detect(const long long* __restrict__ ei) {
    int i = blockIdx.x * blockDim.x + threadIdx.x;
    if (i < N_NODES) g_deg[i] = 0;
    if (i == 0) g_not64 = 0;
    __threadfence();
    if (i < DETECT_N) {
        long long v = ei[i];
        if (v < 0 || v >= N_NODES) atomicOr(&g_not64, 1);
    }
}

// Degree histogram straight from edge_index (row half only).
__global__ void k_deg(const void* __restrict__ eiv) {
    int e = blockIdx.x * blockDim.x + threadIdx.x;
    if (e >= N_EDGES) return;
    long long r64;
    if (g_not64) r64 = ((const int*)eiv)[e];
    else         r64 = ((const long long*)eiv)[e];
    if (r64 >= 0 && r64 < N_NODES) atomicAdd(&g_deg[(int)r64], 1);
}

__global__ void k_dis() {
    int i = blockIdx.x * blockDim.x + threadIdx.x;
    if (i >= N_NODES) return;
    int d = g_deg[i];
    g_dis[i] = (d > 0) ? rsqrtf((float)d) : 0.0f;
}

// ---- exclusive prefix sum over g_deg (3 kernels) ----

__global__ void k_scan1() {
    __shared__ int sh[SCAN_BLOCK];
    int i = blockIdx.x * SCAN_BLOCK + threadIdx.x;
    int v = g_deg[i];
    sh[threadIdx.x] = v;
    __syncthreads();
    for (int off = 1; off < SCAN_BLOCK; off <<= 1) {
        int t = (threadIdx.x >= off) ? sh[threadIdx.x - off] : 0;
        __syncthreads();
        sh[threadIdx.x] += t;
        __syncthreads();
    }
    g_start[i] = sh[threadIdx.x];   // inclusive-within-block (temp)
    if (threadIdx.x == SCAN_BLOCK - 1) g_bsum[blockIdx.x] = sh[threadIdx.x];
}

__global__ void k_scan2() {   // single block of 256 threads, NBLK=250
    __shared__ int sh[256];
    int v = (threadIdx.x < NBLK) ? g_bsum[threadIdx.x] : 0;
    sh[threadIdx.x] = v;
    __syncthreads();
    for (int off = 1; off < 256; off <<= 1) {
        int t = (threadIdx.x >= off) ? sh[threadIdx.x - off] : 0;
        __syncthreads();
        sh[threadIdx.x] += t;
        __syncthreads();
    }
    if (threadIdx.x < NBLK) g_bsumx[threadIdx.x] = sh[threadIdx.x] - v; // exclusive
}

__global__ void k_scan3() {
    int i = blockIdx.x * blockDim.x + threadIdx.x;
    if (i >= N_NODES) return;
    int excl = g_start[i] - g_deg[i] + g_bsumx[i / SCAN_BLOCK];
    g_start[i]  = excl;
    g_cursor[i] = excl;
}

// Fill CSR pairs (col, dis[col]). One random dis gather per edge (row's dis
// is applied once per row in the gather kernels). Row order irrelevant.
__global__ void k_fill(const void* __restrict__ eiv) {
    int e = blockIdx.x * blockDim.x + threadIdx.x;
    if (e >= N_EDGES) return;
    long long r64, c64;
    if (g_not64) {
        const int* ei32 = (const int*)eiv;
        r64 = ei32[e];
        c64 = ei32[N_EDGES + e];
    } else {
        const long long* ei64 = (const long long*)eiv;
        r64 = ei64[e];
        c64 = ei64[(long long)N_EDGES + e];
    }
    if (r64 < 0 || r64 >= N_NODES || c64 < 0 || c64 >= N_NODES) return;
    int r = (int)r64, c = (int)c64;
    float wc = g_dis[c];
    int p = atomicAdd(&g_cursor[r], 1);
    g_csr[p] = make_int2(c, __float_as_int(wc));
}

// ---------------------------------------------------------------------------
// Gathers: 16 threads per row, one 4-element lane each.
//   S[r] = sum_{e in row} dis[col]*x[col];  x_next[r] = dis[r]*S[r]
// ---------------------------------------------------------------------------

// Layer 1: x = emb (fp32, float4 lanes) -> y1 fp16
__global__ void k_gather_l1(const float4* __restrict__ x,
                            uint2* __restrict__ y) {
    int t = blockIdx.x * blockDim.x + threadIdx.x;   // 4,096,000 threads exact
    int r = t >> 4;
    int c = t & 15;
    if (r >= N_NODES) return;
    unsigned gmask = 0xFFFFu << (threadIdx.x & 16);
    int start = g_start[r];
    int end   = g_cursor[r];
    float4 acc = make_float4(0.f, 0.f, 0.f, 0.f);
    for (int base = start; base < end; base += 16) {
        int n = min(16, end - base);
        int2 pr = make_int2(0, 0);
        if (c < n) pr = __ldcs(&g_csr[base + c]);
        #pragma unroll 4
        for (int j = 0; j < n; ++j) {
            int   col = __shfl_sync(gmask, pr.x, j, 16);
            float w   = __int_as_float(__shfl_sync(gmask, pr.y, j, 16));
            float4 v  = __ldg(&x[col * 16 + c]);
            acc.x += w * v.x; acc.y += w * v.y;
            acc.z += w * v.z; acc.w += w * v.w;
        }
    }
    float dr = g_dis[r];
    acc.x *= dr; acc.y *= dr; acc.z *= dr; acc.w *= dr;
    uint2 pk;
    pk.x = h2u(__float22half2_rn(make_float2(acc.x, acc.y)));
    pk.y = h2u(__float22half2_rn(make_float2(acc.z, acc.w)));
    __stcs(&y[r * 16 + c], pk);
}

__device__ __forceinline__ float4 row_gather_h(const uint2* __restrict__ x,
                                               int r, int c, unsigned gmask) {
    int start = g_start[r];
    int end   = g_cursor[r];
    float4 acc = make_float4(0.f, 0.f, 0.f, 0.f);
    for (int base = start; base < end; base += 16) {
        int n = min(16, end - base);
        int2 pr = make_int2(0, 0);
        if (c < n) pr = __ldcs(&g_csr[base + c]);
        #pragma unroll 4
        for (int j = 0; j < n; ++j) {
            int   col = __shfl_sync(gmask, pr.x, j, 16);
            float w   = __int_as_float(__shfl_sync(gmask, pr.y, j, 16));
            uint2 hv  = __ldg(&x[col * 16 + c]);
            float2 f0 = __half22float2(u2h(hv.x));
            float2 f1 = __half22float2(u2h(hv.y));
            acc.x += w * f0.x; acc.y += w * f0.y;
            acc.z += w * f1.x; acc.w += w * f1.y;
        }
    }
    return acc;
}

// Layer 2: y1 fp16 -> y2 fp16
__global__ void k_gather_l2(const uint2* __restrict__ y1,
                            uint2* __restrict__ y2) {
    int t = blockIdx.x * blockDim.x + threadIdx.x;
    int r = t >> 4;
    int c = t & 15;
    if (r >= N_NODES) return;
    unsigned gmask = 0xFFFFu << (threadIdx.x & 16);
    float4 acc = row_gather_h(y1, r, c, gmask);
    float dr = g_dis[r];
    acc.x *= dr; acc.y *= dr; acc.z *= dr; acc.w *= dr;
    uint2 pk;
    pk.x = h2u(__float22half2_rn(make_float2(acc.x, acc.y)));
    pk.y = h2u(__float22half2_rn(make_float2(acc.z, acc.w)));
    __stcs(&y2[r * 16 + c], pk);
}

// Layer 3 + fused epilogue: out = 0.25*(emb + x1 + x2 + dis[r]*S)
__global__ void k_gather_final(const uint2* __restrict__ y2,
                               const float4* __restrict__ emb,
                               const uint2* __restrict__ y1,
                               float4* __restrict__ out) {
    int t = blockIdx.x * blockDim.x + threadIdx.x;
    int r = t >> 4;
    int c = t & 15;
    if (r >= N_NODES) return;
    unsigned gmask = 0xFFFFu << (threadIdx.x & 16);
    float4 acc = row_gather_h(y2, r, c, gmask);
    float dr = g_dis[r];
    int idx = r * 16 + c;
    float4 e0 = __ldcs(&emb[idx]);
    uint2 h1 = __ldcs(&y1[idx]);
    uint2 h2 = __ldcs(&y2[idx]);
    float2 a1lo = __half22float2(u2h(h1.x));
    float2 a1hi = __half22float2(u2h(h1.y));
    float2 a2lo = __half22float2(u2h(h2.x));
    float2 a2hi = __half22float2(u2h(h2.y));
    float4 o;
    o.x = 0.25f * (e0.x + a1lo.x + a2lo.x + dr * acc.x);
    o.y = 0.25f * (e0.y + a1lo.y + a2lo.y + dr * acc.y);
    o.z = 0.25f * (e0.z + a1hi.x + a2hi.x + dr * acc.z);
    o.w = 0.25f * (e0.w + a1hi.y + a2hi.y + dr * acc.w);
    __stcs(&out[idx], o);
}

// ---------------------------------------------------------------------------

extern "C" void kernel_launch(void* const* d_in, const int* in_sizes, int n_in,
                              void* d_out, int out_size) {
    // Input-order detection by element count (dtype-independent):
    // embedding = 16,384,000 elements, edge_index = 8,000,000.
    int ei_idx = 1, emb_idx = 0;
    if (n_in >= 2 && in_sizes[0] == 2 * N_EDGES) { ei_idx = 0; emb_idx = 1; }

    const float* emb = (const float*)d_in[emb_idx];
    const void*  ei  = d_in[ei_idx];
    float*       out = (float*)d_out;

    const int TB = 256;
    const int node_blocks = (N_NODES + TB - 1) / TB;
    const int edge_blocks = (N_EDGES + TB - 1) / TB;
    const int gat_blocks  = (N_NODES * 16 + TB - 1) / TB;   // 4M threads

    __half* h1;  cudaGetSymbolAddress((void**)&h1, g_h1);
    __half* h2;  cudaGetSymbolAddress((void**)&h2, g_h2);

    // ---- preprocess: degrees, dis, CSR ----
    k_zero_detect<<<node_blocks, TB>>>((const long long*)ei);
    k_deg<<<edge_blocks, TB>>>(ei);
    k_dis<<<node_blocks, TB>>>();
    k_scan1<<<NBLK, SCAN_BLOCK>>>();
    k_scan2<<<1, 256>>>();
    k_scan3<<<node_blocks, TB>>>();
    k_fill<<<edge_blocks, TB>>>(ei);

    // ---- 3 gather layers; epilogue fused into the last ----
    k_gather_l1<<<gat_blocks, TB>>>((const float4*)emb, (uint2*)h1);   // x1
    k_gather_l2<<<gat_blocks, TB>>>((const uint2*)h1, (uint2*)h2);     // x2
    k_gather_final<<<gat_blocks, TB>>>((const uint2*)h2,
                                       (const float4*)emb,
                                       (const uint2*)h1,
                                       (float4*)out);
}

// round 9
// speedup vs baseline: 3.7571x; 1.1871x over previous
#include <cuda_runtime.h>
#include <cuda_fp16.h>
#include <cstdint>

// ---------------------------------------------------------------------------
// LightGCN on B200 (sm_100a) — CSR-gather, all-fp16 gathers, folded weights
//   N_NODES = 256000, EMBED_DIM = 64, N_EDGES = 4,000,000, 3 layers
//   Trick: store x'[c] = dis[c]*x[c] (fp16). Gather = pure sum S = sum x'[col].
//   y'_{l+1}[r] = dis[r]^2 * S  (this is dis[r]*x_{l+1}[r], ready for next
//   layer). Epilogue recovers x_l[r] = idis[r]*y'_l[r], idis = sqrt(deg).
//   CSR holds only col (4 B/edge). Math fp32; storage fp16.
// ---------------------------------------------------------------------------

#define NUM_USERS   100000
#define NUM_ST      150000
#define NUM_INTENTS 6000
#define N_NODES     (NUM_USERS + NUM_ST + NUM_INTENTS)   // 256000
#define EMBED_DIM   64
#define N_EDGES     4000000

#define NFLOATS     (N_NODES * EMBED_DIM)        // 16,384,000
#define NF4         (NFLOATS / 4)                // 4,096,000
#define DETECT_N    4096

#define SCAN_BLOCK  1024
#define NBLK        (N_NODES / SCAN_BLOCK)       // 250 (exact)

// half2 <-> u32 reinterpret helpers
__device__ __forceinline__ unsigned h2u(__half2 h) {
    return *reinterpret_cast<unsigned*>(&h);
}
__device__ __forceinline__ __half2 u2h(unsigned u) {
    return *reinterpret_cast<__half2*>(&u);
}

// Scratch (device globals: allocation-guard safe)
__device__ __align__(16) __half g_e [NFLOATS];   // emb' = dis*emb   (fp16)
__device__ __align__(16) __half g_h1[NFLOATS];   // y1' = dis*x1     (fp16)
__device__ __align__(16) __half g_h2[NFLOATS];   // y2' = dis*x2     (fp16)
__device__ float g_dis [N_NODES];    // deg^-1/2 (0 if deg==0)
__device__ float g_idis[N_NODES];    // deg^+1/2 (0 if deg==0)
__device__ int   g_deg[N_NODES];
__device__ int   g_start[N_NODES];     // CSR row start (exclusive scan)
__device__ int   g_cursor[N_NODES];    // fill cursor; after fill = row end
__device__ int   g_bsum[NBLK];
__device__ int   g_bsumx[NBLK];
__device__ int   g_csr_col[N_EDGES];   // col only (4 B/edge)
__device__ int   g_not64;   // 1 => edge data is int32

// ---------------------------------------------------------------------------

// Zero degrees + dtype detection in one launch.
// Genuine int64 indices all lie in [0, N_NODES); int32 data read as int64
// fuses two indices -> value >= 2^32 almost surely.
__global__ void k_zero_detect(const long long* __restrict__ ei) {
    int i = blockIdx.x * blockDim.x + threadIdx.x;
    if (i < N_NODES) g_deg[i] = 0;
    if (i == 0) g_not64 = 0;
    __threadfence();
    if (i < DETECT_N) {
        long long v = ei[i];
        if (v < 0 || v >= N_NODES) atomicOr(&g_not64, 1);
    }
}

// Degree histogram straight from edge_index (row half only).
__global__ void k_deg(const void* __restrict__ eiv) {
    int e = blockIdx.x * blockDim.x + threadIdx.x;
    if (e >= N_EDGES) return;
    long long r64;
    if (g_not64) r64 = ((const int*)eiv)[e];
    else         r64 = ((const long long*)eiv)[e];
    if (r64 >= 0 && r64 < N_NODES) atomicAdd(&g_deg[(int)r64], 1);
}

__global__ void k_dis() {
    int i = blockIdx.x * blockDim.x + threadIdx.x;
    if (i >= N_NODES) return;
    int d = g_deg[i];
    float df = (float)d;
    g_dis[i]  = (d > 0) ? rsqrtf(df) : 0.0f;
    g_idis[i] = (d > 0) ? sqrtf(df)  : 0.0f;
}

// ---- exclusive prefix sum over g_deg (3 kernels) ----

__global__ void k_scan1() {
    __shared__ int sh[SCAN_BLOCK];
    int i = blockIdx.x * SCAN_BLOCK + threadIdx.x;
    int v = g_deg[i];
    sh[threadIdx.x] = v;
    __syncthreads();
    for (int off = 1; off < SCAN_BLOCK; off <<= 1) {
        int t = (threadIdx.x >= off) ? sh[threadIdx.x - off] : 0;
        __syncthreads();
        sh[threadIdx.x] += t;
        __syncthreads();
    }
    g_start[i] = sh[threadIdx.x];   // inclusive-within-block (temp)
    if (threadIdx.x == SCAN_BLOCK - 1) g_bsum[blockIdx.x] = sh[threadIdx.x];
}

__global__ void k_scan2() {   // single block of 256 threads, NBLK=250
    __shared__ int sh[256];
    int v = (threadIdx.x < NBLK) ? g_bsum[threadIdx.x] : 0;
    sh[threadIdx.x] = v;
    __syncthreads();
    for (int off = 1; off < 256; off <<= 1) {
        int t = (threadIdx.x >= off) ? sh[threadIdx.x - off] : 0;
        __syncthreads();
        sh[threadIdx.x] += t;
        __syncthreads();
    }
    if (threadIdx.x < NBLK) g_bsumx[threadIdx.x] = sh[threadIdx.x] - v; // exclusive
}

__global__ void k_scan3() {
    int i = blockIdx.x * blockDim.x + threadIdx.x;
    if (i >= N_NODES) return;
    int excl = g_start[i] - g_deg[i] + g_bsumx[i / SCAN_BLOCK];
    g_start[i]  = excl;
    g_cursor[i] = excl;
}

// Fill CSR: col only. No weight gather needed (weights folded into states).
__global__ void k_fill(const void* __restrict__ eiv) {
    int e = blockIdx.x * blockDim.x + threadIdx.x;
    if (e >= N_EDGES) return;
    long long r64, c64;
    if (g_not64) {
        const int* ei32 = (const int*)eiv;
        r64 = ei32[e];
        c64 = ei32[N_EDGES + e];
    } else {
        const long long* ei64 = (const long long*)eiv;
        r64 = ei64[e];
        c64 = ei64[(long long)N_EDGES + e];
    }
    if (r64 < 0 || r64 >= N_NODES || c64 < 0 || c64 >= N_NODES) return;
    int r = (int)r64, c = (int)c64;
    int p = atomicAdd(&g_cursor[r], 1);
    g_csr_col[p] = c;
}

// emb' = fp16(dis[n] * emb[n])  — one uint2 (4 halves) per thread
__global__ void k_prescale(const float4* __restrict__ emb,
                           uint2* __restrict__ ep) {
    int i = blockIdx.x * blockDim.x + threadIdx.x;
    if (i >= NF4) return;
    int n = i >> 4;
    float dr = g_dis[n];
    float4 v = __ldcs(&emb[i]);
    uint2 pk;
    pk.x = h2u(__float22half2_rn(make_float2(dr * v.x, dr * v.y)));
    pk.y = h2u(__float22half2_rn(make_float2(dr * v.z, dr * v.w)));
    __stcs(&ep[i], pk);
}

// ---------------------------------------------------------------------------
// Gathers: 16 threads per row, one 4-element lane each.
//   S[r] = sum_{e in row} x'[col]   (pure unweighted sum, weights pre-folded)
// ---------------------------------------------------------------------------

__device__ __forceinline__ float4 row_gather_sum(const uint2* __restrict__ x,
                                                 int r, int c, unsigned gmask) {
    int start = g_start[r];
    int end   = g_cursor[r];
    float4 acc = make_float4(0.f, 0.f, 0.f, 0.f);
    for (int base = start; base < end; base += 16) {
        int n = min(16, end - base);
        int cl = 0;
        if (c < n) cl = __ldcs(&g_csr_col[base + c]);
        #pragma unroll 4
        for (int j = 0; j < n; ++j) {
            int col  = __shfl_sync(gmask, cl, j, 16);
            uint2 hv = __ldg(&x[col * 16 + c]);
            float2 f0 = __half22float2(u2h(hv.x));
            float2 f1 = __half22float2(u2h(hv.y));
            acc.x += f0.x; acc.y += f0.y;
            acc.z += f1.x; acc.w += f1.y;
        }
    }
    return acc;
}

// Layers 1..2: y'[r] = fp16(dis[r]^2 * S)   (= dis[r]*x_{l+1}[r])
__global__ void k_gather(const uint2* __restrict__ x,
                         uint2* __restrict__ y) {
    int t = blockIdx.x * blockDim.x + threadIdx.x;   // 4,096,000 threads exact
    int r = t >> 4;
    int c = t & 15;
    if (r >= N_NODES) return;
    unsigned gmask = 0xFFFFu << (threadIdx.x & 16);
    float4 acc = row_gather_sum(x, r, c, gmask);
    float dr = g_dis[r];
    float s = dr * dr;
    uint2 pk;
    pk.x = h2u(__float22half2_rn(make_float2(s * acc.x, s * acc.y)));
    pk.y = h2u(__float22half2_rn(make_float2(s * acc.z, s * acc.w)));
    __stcs(&y[r * 16 + c], pk);
}

// Layer 3 + fused epilogue:
//   out = 0.25*(emb + idis[r]*(y1'+y2') + dis[r]*S3)
__global__ void k_gather_final(const uint2* __restrict__ y2,
                               const float4* __restrict__ emb,
                               const uint2* __restrict__ y1,
                               float4* __restrict__ out) {
    int t = blockIdx.x * blockDim.x + threadIdx.x;
    int r = t >> 4;
    int c = t & 15;
    if (r >= N_NODES) return;
    unsigned gmask = 0xFFFFu << (threadIdx.x & 16);
    float4 acc = row_gather_sum(y2, r, c, gmask);
    float dr = g_dis[r];
    float ir = g_idis[r];
    int idx = r * 16 + c;
    float4 e0 = __ldcs(&emb[idx]);
    uint2 h1 = __ldcs(&y1[idx]);
    uint2 h2 = __ldcs(&y2[idx]);
    float2 a1lo = __half22float2(u2h(h1.x));
    float2 a1hi = __half22float2(u2h(h1.y));
    float2 a2lo = __half22float2(u2h(h2.x));
    float2 a2hi = __half22float2(u2h(h2.y));
    float4 o;
    o.x = 0.25f * (e0.x + ir * (a1lo.x + a2lo.x) + dr * acc.x);
    o.y = 0.25f * (e0.y + ir * (a1lo.y + a2lo.y) + dr * acc.y);
    o.z = 0.25f * (e0.z + ir * (a1hi.x + a2hi.x) + dr * acc.z);
    o.w = 0.25f * (e0.w + ir * (a1hi.y + a2hi.y) + dr * acc.w);
    __stcs(&out[idx], o);
}

// ---------------------------------------------------------------------------

extern "C" void kernel_launch(void* const* d_in, const int* in_sizes, int n_in,
                              void* d_out, int out_size) {
    // Input-order detection by element count (dtype-independent):
    // embedding = 16,384,000 elements, edge_index = 8,000,000.
    int ei_idx = 1, emb_idx = 0;
    if (n_in >= 2 && in_sizes[0] == 2 * N_EDGES) { ei_idx = 0; emb_idx = 1; }

    const float* emb = (const float*)d_in[emb_idx];
    const void*  ei  = d_in[ei_idx];
    float*       out = (float*)d_out;

    const int TB = 256;
    const int node_blocks = (N_NODES + TB - 1) / TB;
    const int edge_blocks = (N_EDGES + TB - 1) / TB;
    const int f4_blocks   = (NF4 + TB - 1) / TB;
    const int gat_blocks  = (N_NODES * 16 + TB - 1) / TB;   // 4M threads

    __half* e;   cudaGetSymbolAddress((void**)&e,  g_e);
    __half* h1;  cudaGetSymbolAddress((void**)&h1, g_h1);
    __half* h2;  cudaGetSymbolAddress((void**)&h2, g_h2);

    // ---- preprocess: degrees, dis, CSR, fp16 prescaled emb ----
    k_zero_detect<<<node_blocks, TB>>>((const long long*)ei);
    k_deg<<<edge_blocks, TB>>>(ei);
    k_dis<<<node_blocks, TB>>>();
    k_scan1<<<NBLK, SCAN_BLOCK>>>();
    k_scan2<<<1, 256>>>();
    k_scan3<<<node_blocks, TB>>>();
    k_fill<<<edge_blocks, TB>>>(ei);
    k_prescale<<<f4_blocks, TB>>>((const float4*)emb, (uint2*)e);

    // ---- 3 gather layers; epilogue fused into the last ----
    k_gather<<<gat_blocks, TB>>>((const uint2*)e,  (uint2*)h1);   // y1'
    k_gather<<<gat_blocks, TB>>>((const uint2*)h1, (uint2*)h2);   // y2'
    k_gather_final<<<gat_blocks, TB>>>((const uint2*)h2,
                                       (const float4*)emb,
                                       (const uint2*)h1,
                                       (float4*)out);
}